// round 13
// baseline (speedup 1.0000x reference)
#include <cuda_runtime.h>
#include <cuda_fp16.h>
#include <cstdint>

// ---------------------------------------------------------------------------
// Problem constants
// ---------------------------------------------------------------------------
#define IN_DIM   4096
#define OUT_DIM  4096
#define BATCH    8192
#define HASH_A   10007
#define HASH_B   20011
#define HASH_C_L 120027      // HASH_C * LAYER_ID(3)
#define SGN_A    4099
#define SGN_B    6151
#define SGN_C_L  44661       // SIGN_HASH_C * 3

// GEMM tiling (fp16): K-stage 64 halves = 128B rows
#define TM 128
#define TN 128
#define TK 64
#define NSLOT 2              // double-buffered smem (64KB -> 3 CTAs/SM)
#define KTILES (IN_DIM / TK) // 64

#define A_TILE_BYTES (TM * 128)          // 16384
#define B_TILE_BYTES (TN * 128)          // 16384
#define STAGE_BYTES  (A_TILE_BYTES + B_TILE_BYTES)   // 32768
#define SMEM_TOTAL   (NSLOT * STAGE_BYTES)           // 65536

// Tail split-K: last 9 m-bands (288 tiles, rows >= 7040) run as 2 half-K CTAs
#define N_TILES_X   (OUT_DIM / TN)                   // 32
#define FULL_TILES  (55 * N_TILES_X)                 // 1760 (m-bands 0..54)
#define TAIL_TILES  (2048 - FULL_TILES)              // 288
#define GRID_TOTAL  (FULL_TILES + 2 * TAIL_TILES)    // 2336
#define TAIL_ROW0   (55 * TM)                        // 7040

// Fused prep kernel grid split
#define W_BLOCKS ((OUT_DIM * IN_DIM / 8) / 256)              // 8192
#define X_BLOCKS (((size_t)BATCH * IN_DIM / 8) / 256)        // 16384

// ---------------------------------------------------------------------------
// Scratch: fp16 weight matrix [OUT_DIM, IN_DIM] K-major, fp16 copy of x
// ---------------------------------------------------------------------------
__device__ __half g_Wh[(size_t)OUT_DIM * IN_DIM];    // 32 MB
__device__ __half g_xh[(size_t)BATCH * IN_DIM];      // 64 MB

// ---------------------------------------------------------------------------
// PTX helpers (base-PTX only: cp.async, ldmatrix, mma.sync)
// ---------------------------------------------------------------------------
__device__ __forceinline__ uint32_t smem_u32(const void* p) {
    uint32_t a;
    asm("{ .reg .u64 t; cvta.to.shared.u64 t, %1; cvt.u32.u64 %0, t; }" : "=r"(a) : "l"(p));
    return a;
}

__device__ __forceinline__ void cp_async16(uint32_t saddr, const void* gptr) {
    asm volatile("cp.async.cg.shared.global [%0], [%1], 16;" :: "r"(saddr), "l"(gptr) : "memory");
}
#define CP_COMMIT() asm volatile("cp.async.commit_group;" ::: "memory")
#define CP_WAIT0()  asm volatile("cp.async.wait_group 0;" ::: "memory")

__device__ __forceinline__ void ldsm4(uint32_t* r, uint32_t addr) {
    asm volatile("ldmatrix.sync.aligned.m8n8.x4.shared.b16 {%0,%1,%2,%3}, [%4];"
        : "=r"(r[0]), "=r"(r[1]), "=r"(r[2]), "=r"(r[3]) : "r"(addr));
}

__device__ __forceinline__ void mma_f16(float* c, const uint32_t* a, uint32_t b0, uint32_t b1) {
    asm volatile(
        "mma.sync.aligned.m16n8k16.row.col.f32.f16.f16.f32 "
        "{%0,%1,%2,%3}, {%4,%5,%6,%7}, {%8,%9}, {%0,%1,%2,%3};"
        : "+f"(c[0]), "+f"(c[1]), "+f"(c[2]), "+f"(c[3])
        : "r"(a[0]), "r"(a[1]), "r"(a[2]), "r"(a[3]), "r"(b0), "r"(b1));
}

// ---------------------------------------------------------------------------
// Kernel 1 (fused prep):
//   blocks [0, W_BLOCKS)            : W[o][i] = fp16(codebook[hash] * sign)
//   blocks [W_BLOCKS, W_BLOCKS+X_B) : xh = fp16(x)
// ---------------------------------------------------------------------------
__global__ void __launch_bounds__(256) prep_kernel(const float* __restrict__ cb,
                                                   const float* __restrict__ x,
                                                   __half* __restrict__ W,
                                                   __half* __restrict__ xh) {
    int bid = blockIdx.x;
    if (bid < W_BLOCKS) {
        int t = bid * blockDim.x + threadIdx.x;
        int base = t << 3;
        int o = base >> 12;
        int i = base & (IN_DIM - 1);
        int h0 = o * HASH_A + HASH_C_L;
        int s0 = o * SGN_A + SGN_C_L;
        __half w[8];
#pragma unroll
        for (int j = 0; j < 8; j++) {
            int ij = i + j;
            int h = (h0 + ij * HASH_B) & 65535;
            int sgn = (s0 + ij * SGN_B) & 1;
            float v = __ldg(cb + h);
            v = sgn ? v : -v;                            // bit 1 -> +1, bit 0 -> -1
            w[j] = __float2half_rn(v);
        }
        *reinterpret_cast<uint4*>(W + base) = *reinterpret_cast<uint4*>(w);
    } else {
        size_t t = (size_t)(bid - W_BLOCKS) * blockDim.x + threadIdx.x;
        size_t base = t << 3;
        float4 a = reinterpret_cast<const float4*>(x + base)[0];
        float4 b = reinterpret_cast<const float4*>(x + base)[1];
        __half2 h[4];
        h[0] = __floats2half2_rn(a.x, a.y);
        h[1] = __floats2half2_rn(a.z, a.w);
        h[2] = __floats2half2_rn(b.x, b.y);
        h[3] = __floats2half2_rn(b.z, b.w);
        *reinterpret_cast<uint4*>(xh + base) = *reinterpret_cast<uint4*>(h);
    }
}

// ---------------------------------------------------------------------------
// Kernel 2: pipelined fp16 mma.sync GEMM + split-K2 tail
//   bid < FULL_TILES            : full-K tile, plain stores
//   bid >= FULL_TILES           : pairs (tile, khalf); K range 32 ktiles;
//                                 atomicAdd onto pre-zeroed rows >= 7040.
//                                 Exactly 2 float contributors onto 0 ->
//                                 bitwise deterministic (fp add commutes).
// ---------------------------------------------------------------------------
__global__ void __launch_bounds__(128, 3) gemm_kernel(
    const __half* __restrict__ x, const __half* __restrict__ W,
    const float* __restrict__ bias, float* __restrict__ out) {
    extern __shared__ char smem[];
    uint32_t sb = smem_u32(smem);

    int tid  = threadIdx.x;
    int lane = tid & 31;
    int wid  = tid >> 5;
    int wm   = wid >> 1;           // warp row (0..1)
    int wn   = wid & 1;            // warp col (0..1)

    // tile / K-range decode
    int bid = blockIdx.x;
    int tile, ktA, ktB, split;
    if (bid < FULL_TILES) {
        tile = bid; ktA = 0; ktB = KTILES; split = 0;
    } else {
        int s = bid - FULL_TILES;
        tile  = FULL_TILES + (s >> 1);
        ktA   = (s & 1) * (KTILES / 2);
        ktB   = ktA + KTILES / 2;
        split = 1;
    }
    int n0 = (tile & (N_TILES_X - 1)) * TN;
    int m0 = (tile / N_TILES_X) * TM;

    // ---- cp.async per-thread mapping --------------------------------------
    int cp_r     = tid >> 3;                 // base row (step adds 16)
    int cp_c     = tid & 7;                  // chunk
    int cp_csw   = cp_c ^ (cp_r & 7);        // swizzled chunk
    uint32_t cpA = sb + cp_r * 128 + cp_csw * 16;
    uint32_t cpB = cpA + A_TILE_BYTES;
    const char* gA = (const char*)(x + (size_t)(m0 + cp_r) * IN_DIM + cp_c * 8) + (size_t)ktA * 128;
    const char* gB = (const char*)(W + (size_t)(n0 + cp_r) * IN_DIM + cp_c * 8) + (size_t)ktA * 128;

    // ---- ldmatrix per-thread addresses ------------------------------------
    int hi  = lane >> 4;
    int swz = lane & 7;
    uint32_t aBase = sb + (wm * 64 + (lane & 15)) * 128;
    uint32_t bBase = sb + A_TILE_BYTES + (wn * 64 + (lane & 15)) * 128;
    uint32_t co[4];
#pragma unroll
    for (int ks = 0; ks < 4; ks++) co[ks] = (uint32_t)(((2 * ks + hi) ^ swz) << 4);

    float c[4][8][4];
#pragma unroll
    for (int mb = 0; mb < 4; mb++)
#pragma unroll
        for (int j = 0; j < 8; j++)
#pragma unroll
            for (int q = 0; q < 4; q++) c[mb][j][q] = 0.0f;

    // ---- prologue: first stage into slot 0 --------------------------------
    {
#pragma unroll
        for (int s = 0; s < 8; s++) {
            cp_async16(cpA + s * 2048, gA + (size_t)s * 16 * IN_DIM * 2);
            cp_async16(cpB + s * 2048, gB + (size_t)s * 16 * IN_DIM * 2);
        }
        CP_COMMIT();
    }

    // ---- main loop: wait(kt) -> sync -> issue(kt+1) -> compute(kt) --------
    int nkt = ktB - ktA;
    for (int r = 0; r < nkt; r++) {
        CP_WAIT0();
        __syncthreads();

        if (r + 1 < nkt) {
            uint32_t slot = (uint32_t)((r + 1) & 1) * STAGE_BYTES;
            const char* ga = gA + (size_t)(r + 1) * 128;
            const char* gb = gB + (size_t)(r + 1) * 128;
#pragma unroll
            for (int s = 0; s < 8; s++) {
                cp_async16(cpA + slot + s * 2048, ga + (size_t)s * 16 * IN_DIM * 2);
                cp_async16(cpB + slot + s * 2048, gb + (size_t)s * 16 * IN_DIM * 2);
            }
            CP_COMMIT();
        }

        // compute on slot r&1
        uint32_t slot = (uint32_t)(r & 1) * STAGE_BYTES;
        uint32_t aS = aBase + slot;
        uint32_t bS = bBase + slot;
#pragma unroll
        for (int ks = 0; ks < 4; ks++) {
            uint32_t a[4][4];
            uint32_t b[4][4];
#pragma unroll
            for (int mb = 0; mb < 4; mb++) ldsm4(a[mb], aS + mb * 2048 + co[ks]);
#pragma unroll
            for (int p = 0; p < 4; p++)    ldsm4(b[p], bS + p * 2048 + co[ks]);
#pragma unroll
            for (int mb = 0; mb < 4; mb++)
#pragma unroll
                for (int j = 0; j < 8; j++) {
                    int p = j >> 1, o = j & 1;
                    mma_f16(c[mb][j], a[mb], b[p][o], b[p][o + 2]);
                }
        }
    }

    // ---- epilogue ---------------------------------------------------------
    int row0 = m0 + wm * 64 + (lane >> 2);
    int col0 = n0 + wn * 64 + 2 * (lane & 3);
    float2 bv[8];
#pragma unroll
    for (int j = 0; j < 8; j++) {
        if (ktA == 0) {                      // bias contributed once (khalf 0 / full)
            bv[j].x = __ldg(bias + col0 + j * 8);
            bv[j].y = __ldg(bias + col0 + j * 8 + 1);
        } else {
            bv[j].x = 0.0f; bv[j].y = 0.0f;
        }
    }
#pragma unroll
    for (int mb = 0; mb < 4; mb++) {
        float* r0p = out + (size_t)(row0 + mb * 16) * OUT_DIM;
        float* r1p = r0p + 8 * OUT_DIM;
#pragma unroll
        for (int j = 0; j < 8; j++) {
            float2 v0 = { c[mb][j][0] + bv[j].x, c[mb][j][1] + bv[j].y };
            float2 v1 = { c[mb][j][2] + bv[j].x, c[mb][j][3] + bv[j].y };
            if (!split) {
                *reinterpret_cast<float2*>(r0p + col0 + j * 8) = v0;
                *reinterpret_cast<float2*>(r1p + col0 + j * 8) = v1;
            } else {
                atomicAdd(r0p + col0 + j * 8,     v0.x);
                atomicAdd(r0p + col0 + j * 8 + 1, v0.y);
                atomicAdd(r1p + col0 + j * 8,     v1.x);
                atomicAdd(r1p + col0 + j * 8 + 1, v1.y);
            }
        }
    }
}

// ---------------------------------------------------------------------------
// Host launch
// ---------------------------------------------------------------------------
extern "C" void kernel_launch(void* const* d_in, const int* in_sizes, int n_in,
                              void* d_out, int out_size) {
    const float* x        = (const float*)d_in[0];
    const float* codebook = (const float*)d_in[1];
    const float* bias     = (const float*)d_in[2];
    float* out            = (float*)d_out;

    void* wptr = nullptr;
    void* xptr = nullptr;
    cudaGetSymbolAddress(&wptr, g_Wh);
    cudaGetSymbolAddress(&xptr, g_xh);

    // 0) zero the split-K tail region (rows TAIL_ROW0..BATCH) — atomic targets
    cudaMemsetAsync(out + (size_t)TAIL_ROW0 * OUT_DIM, 0,
                    (size_t)(BATCH - TAIL_ROW0) * OUT_DIM * sizeof(float), 0);

    // 1) fused prep: materialize W (fp16) + convert x (fp16) in one launch
    prep_kernel<<<(unsigned)(W_BLOCKS + X_BLOCKS), 256>>>(
        codebook, x, (__half*)wptr, (__half*)xptr);

    // 2) GEMM (full tiles + split-K2 tail)
    static bool attr_set = false;
    if (!attr_set) {
        cudaFuncSetAttribute(gemm_kernel, cudaFuncAttributeMaxDynamicSharedMemorySize, SMEM_TOTAL);
        attr_set = true;
    }
    gemm_kernel<<<GRID_TOTAL, 128, SMEM_TOTAL>>>(
        (const __half*)xptr, (const __half*)wptr, bias, out);
}

// round 14
// speedup vs baseline: 1.0721x; 1.0721x over previous
#include <cuda_runtime.h>
#include <cuda_fp16.h>
#include <cstdint>

// ---------------------------------------------------------------------------
// Problem constants
// ---------------------------------------------------------------------------
#define IN_DIM   4096
#define OUT_DIM  4096
#define BATCH    8192
#define HASH_A   10007
#define HASH_B   20011
#define HASH_C_L 120027      // HASH_C * LAYER_ID(3)
#define SGN_A    4099
#define SGN_B    6151
#define SGN_C_L  44661       // SIGN_HASH_C * 3

// GEMM tiling (fp16): K-stage 64 halves = 128B rows
#define TM 128
#define TN 128
#define TK 64
#define NSLOT 2              // double-buffered smem (64KB -> 3 CTAs/SM)
#define KTILES (IN_DIM / TK) // 64

#define A_TILE_BYTES (TM * 128)          // 16384
#define B_TILE_BYTES (TN * 128)          // 16384
#define STAGE_BYTES  (A_TILE_BYTES + B_TILE_BYTES)   // 32768
#define SMEM_TOTAL   (NSLOT * STAGE_BYTES)           // 65536

// Tail split-K: last 9 m-bands (288 tiles, rows >= 7040) run as 2 half-K CTAs
#define N_TILES_X   (OUT_DIM / TN)                   // 32
#define FULL_TILES  (55 * N_TILES_X)                 // 1760 (m-bands 0..54)
#define TAIL_TILES  (2048 - FULL_TILES)              // 288
#define GRID_TOTAL  (FULL_TILES + 2 * TAIL_TILES)    // 2336
#define TAIL_ROW0   (55 * TM)                        // 7040

// Fused prep kernel grid split
#define W_BLOCKS ((OUT_DIM * IN_DIM / 8) / 256)              // 8192
#define X_BLOCKS (((size_t)BATCH * IN_DIM / 8) / 256)        // 16384

// ---------------------------------------------------------------------------
// Scratch: fp16 weight matrix [OUT_DIM, IN_DIM] K-major, fp16 copy of x
// ---------------------------------------------------------------------------
__device__ __half g_Wh[(size_t)OUT_DIM * IN_DIM];    // 32 MB
__device__ __half g_xh[(size_t)BATCH * IN_DIM];      // 64 MB

// ---------------------------------------------------------------------------
// PTX helpers (base-PTX only: cp.async, ldmatrix, mma.sync)
// ---------------------------------------------------------------------------
__device__ __forceinline__ uint32_t smem_u32(const void* p) {
    uint32_t a;
    asm("{ .reg .u64 t; cvta.to.shared.u64 t, %1; cvt.u32.u64 %0, t; }" : "=r"(a) : "l"(p));
    return a;
}

__device__ __forceinline__ void cp_async16(uint32_t saddr, const void* gptr) {
    asm volatile("cp.async.cg.shared.global [%0], [%1], 16;" :: "r"(saddr), "l"(gptr) : "memory");
}
#define CP_COMMIT() asm volatile("cp.async.commit_group;" ::: "memory")
#define CP_WAIT0()  asm volatile("cp.async.wait_group 0;" ::: "memory")

__device__ __forceinline__ void ldsm4(uint32_t* r, uint32_t addr) {
    asm volatile("ldmatrix.sync.aligned.m8n8.x4.shared.b16 {%0,%1,%2,%3}, [%4];"
        : "=r"(r[0]), "=r"(r[1]), "=r"(r[2]), "=r"(r[3]) : "r"(addr));
}

__device__ __forceinline__ void mma_f16(float* c, const uint32_t* a, uint32_t b0, uint32_t b1) {
    asm volatile(
        "mma.sync.aligned.m16n8k16.row.col.f32.f16.f16.f32 "
        "{%0,%1,%2,%3}, {%4,%5,%6,%7}, {%8,%9}, {%0,%1,%2,%3};"
        : "+f"(c[0]), "+f"(c[1]), "+f"(c[2]), "+f"(c[3])
        : "r"(a[0]), "r"(a[1]), "r"(a[2]), "r"(a[3]), "r"(b0), "r"(b1));
}

// ---------------------------------------------------------------------------
// Kernel 1 (fused prep):
//   blocks [0, W_BLOCKS)            : W[o][i] = fp16(codebook[hash] * sign)
//   blocks [W_BLOCKS, W_BLOCKS+X_B) : xh = fp16(x)
// ---------------------------------------------------------------------------
__global__ void __launch_bounds__(256) prep_kernel(const float* __restrict__ cb,
                                                   const float* __restrict__ x,
                                                   __half* __restrict__ W,
                                                   __half* __restrict__ xh) {
    int bid = blockIdx.x;
    if (bid < W_BLOCKS) {
        int t = bid * blockDim.x + threadIdx.x;
        int base = t << 3;
        int o = base >> 12;
        int i = base & (IN_DIM - 1);
        int h0 = o * HASH_A + HASH_C_L;
        int s0 = o * SGN_A + SGN_C_L;
        __half w[8];
#pragma unroll
        for (int j = 0; j < 8; j++) {
            int ij = i + j;
            int h = (h0 + ij * HASH_B) & 65535;
            int sgn = (s0 + ij * SGN_B) & 1;
            float v = __ldg(cb + h);
            v = sgn ? v : -v;                            // bit 1 -> +1, bit 0 -> -1
            w[j] = __float2half_rn(v);
        }
        *reinterpret_cast<uint4*>(W + base) = *reinterpret_cast<uint4*>(w);
    } else {
        size_t t = (size_t)(bid - W_BLOCKS) * blockDim.x + threadIdx.x;
        size_t base = t << 3;
        float4 a = reinterpret_cast<const float4*>(x + base)[0];
        float4 b = reinterpret_cast<const float4*>(x + base)[1];
        __half2 h[4];
        h[0] = __floats2half2_rn(a.x, a.y);
        h[1] = __floats2half2_rn(a.z, a.w);
        h[2] = __floats2half2_rn(b.x, b.y);
        h[3] = __floats2half2_rn(b.z, b.w);
        *reinterpret_cast<uint4*>(xh + base) = *reinterpret_cast<uint4*>(h);
    }
}

// ---------------------------------------------------------------------------
// Mainloop template: compile-time trip count so both the full-K (64) and
// half-K (32) paths get the round-12 codegen (unrolled slot parity, constant
// address strength reduction). Includes the stage-0 prologue.
// ---------------------------------------------------------------------------
template <int NKT>
__device__ __forceinline__ void mainloop(
    uint32_t cpA, uint32_t cpB, const char* gA, const char* gB,
    uint32_t aBase, uint32_t bBase, const uint32_t* co, float c[4][8][4]) {
    // prologue: stage 0 into slot 0
#pragma unroll
    for (int s = 0; s < 8; s++) {
        cp_async16(cpA + s * 2048, gA + (size_t)s * 16 * IN_DIM * 2);
        cp_async16(cpB + s * 2048, gB + (size_t)s * 16 * IN_DIM * 2);
    }
    CP_COMMIT();

    for (int kt = 0; kt < NKT; kt++) {
        CP_WAIT0();
        __syncthreads();

        if (kt + 1 < NKT) {
            int nk = kt + 1;
            uint32_t slot = (uint32_t)(nk & 1) * STAGE_BYTES;
            const char* ga = gA + (size_t)nk * 128;
            const char* gb = gB + (size_t)nk * 128;
#pragma unroll
            for (int s = 0; s < 8; s++) {
                cp_async16(cpA + slot + s * 2048, ga + (size_t)s * 16 * IN_DIM * 2);
                cp_async16(cpB + slot + s * 2048, gb + (size_t)s * 16 * IN_DIM * 2);
            }
            CP_COMMIT();
        }

        uint32_t slot = (uint32_t)(kt & 1) * STAGE_BYTES;
        uint32_t aS = aBase + slot;
        uint32_t bS = bBase + slot;
#pragma unroll
        for (int ks = 0; ks < 4; ks++) {
            uint32_t a[4][4];
            uint32_t b[4][4];
#pragma unroll
            for (int mb = 0; mb < 4; mb++) ldsm4(a[mb], aS + mb * 2048 + co[ks]);
#pragma unroll
            for (int p = 0; p < 4; p++)    ldsm4(b[p], bS + p * 2048 + co[ks]);
#pragma unroll
            for (int mb = 0; mb < 4; mb++)
#pragma unroll
                for (int j = 0; j < 8; j++) {
                    int p = j >> 1, o = j & 1;
                    mma_f16(c[mb][j], a[mb], b[p][o], b[p][o + 2]);
                }
        }
    }
}

// ---------------------------------------------------------------------------
// Kernel 2: pipelined fp16 mma.sync GEMM + split-K2 tail
//   bid < FULL_TILES : full-K tile (mainloop<64>), plain stores
//   bid >= FULL_TILES: pairs (tile, khalf), mainloop<32>, atomicAdd onto
//                      pre-zeroed rows >= 7040 (2 contributors -> deterministic)
// ---------------------------------------------------------------------------
__global__ void __launch_bounds__(128, 3) gemm_kernel(
    const __half* __restrict__ x, const __half* __restrict__ W,
    const float* __restrict__ bias, float* __restrict__ out) {
    extern __shared__ char smem[];
    uint32_t sb = smem_u32(smem);

    int tid  = threadIdx.x;
    int lane = tid & 31;
    int wid  = tid >> 5;
    int wm   = wid >> 1;           // warp row (0..1)
    int wn   = wid & 1;            // warp col (0..1)

    // tile / K-range decode (once, outside the loops)
    int bid = blockIdx.x;
    int tile, ktA, split;
    if (bid < FULL_TILES) {
        tile = bid; ktA = 0; split = 0;
    } else {
        int s = bid - FULL_TILES;
        tile  = FULL_TILES + (s >> 1);
        ktA   = (s & 1) * (KTILES / 2);
        split = 1;
    }
    int n0 = (tile & (N_TILES_X - 1)) * TN;
    int m0 = (tile / N_TILES_X) * TM;

    // ---- cp.async per-thread mapping --------------------------------------
    int cp_r     = tid >> 3;                 // base row (step adds 16)
    int cp_c     = tid & 7;                  // chunk
    int cp_csw   = cp_c ^ (cp_r & 7);        // swizzled chunk
    uint32_t cpA = sb + cp_r * 128 + cp_csw * 16;
    uint32_t cpB = cpA + A_TILE_BYTES;
    const char* gA = (const char*)(x + (size_t)(m0 + cp_r) * IN_DIM + cp_c * 8) + (size_t)ktA * 128;
    const char* gB = (const char*)(W + (size_t)(n0 + cp_r) * IN_DIM + cp_c * 8) + (size_t)ktA * 128;

    // ---- ldmatrix per-thread addresses ------------------------------------
    int hi  = lane >> 4;
    int swz = lane & 7;
    uint32_t aBase = sb + (wm * 64 + (lane & 15)) * 128;
    uint32_t bBase = sb + A_TILE_BYTES + (wn * 64 + (lane & 15)) * 128;
    uint32_t co[4];
#pragma unroll
    for (int ks = 0; ks < 4; ks++) co[ks] = (uint32_t)(((2 * ks + hi) ^ swz) << 4);

    float c[4][8][4];
#pragma unroll
    for (int mb = 0; mb < 4; mb++)
#pragma unroll
        for (int j = 0; j < 8; j++)
#pragma unroll
            for (int q = 0; q < 4; q++) c[mb][j][q] = 0.0f;

    // ---- mainloop: compile-time trip count per path -----------------------
    if (!split) {
        mainloop<KTILES>(cpA, cpB, gA, gB, aBase, bBase, co, c);
    } else {
        mainloop<KTILES / 2>(cpA, cpB, gA, gB, aBase, bBase, co, c);
    }

    // ---- epilogue ---------------------------------------------------------
    int row0 = m0 + wm * 64 + (lane >> 2);
    int col0 = n0 + wn * 64 + 2 * (lane & 3);
    float2 bv[8];
#pragma unroll
    for (int j = 0; j < 8; j++) {
        if (ktA == 0) {                      // bias contributed once (khalf 0 / full)
            bv[j].x = __ldg(bias + col0 + j * 8);
            bv[j].y = __ldg(bias + col0 + j * 8 + 1);
        } else {
            bv[j].x = 0.0f; bv[j].y = 0.0f;
        }
    }
#pragma unroll
    for (int mb = 0; mb < 4; mb++) {
        float* r0p = out + (size_t)(row0 + mb * 16) * OUT_DIM;
        float* r1p = r0p + 8 * OUT_DIM;
#pragma unroll
        for (int j = 0; j < 8; j++) {
            float2 v0 = { c[mb][j][0] + bv[j].x, c[mb][j][1] + bv[j].y };
            float2 v1 = { c[mb][j][2] + bv[j].x, c[mb][j][3] + bv[j].y };
            if (!split) {
                *reinterpret_cast<float2*>(r0p + col0 + j * 8) = v0;
                *reinterpret_cast<float2*>(r1p + col0 + j * 8) = v1;
            } else {
                atomicAdd(r0p + col0 + j * 8,     v0.x);
                atomicAdd(r0p + col0 + j * 8 + 1, v0.y);
                atomicAdd(r1p + col0 + j * 8,     v1.x);
                atomicAdd(r1p + col0 + j * 8 + 1, v1.y);
            }
        }
    }
}

// ---------------------------------------------------------------------------
// Host launch
// ---------------------------------------------------------------------------
extern "C" void kernel_launch(void* const* d_in, const int* in_sizes, int n_in,
                              void* d_out, int out_size) {
    const float* x        = (const float*)d_in[0];
    const float* codebook = (const float*)d_in[1];
    const float* bias     = (const float*)d_in[2];
    float* out            = (float*)d_out;

    void* wptr = nullptr;
    void* xptr = nullptr;
    cudaGetSymbolAddress(&wptr, g_Wh);
    cudaGetSymbolAddress(&xptr, g_xh);

    // 0) zero the split-K tail region (rows TAIL_ROW0..BATCH) — atomic targets
    cudaMemsetAsync(out + (size_t)TAIL_ROW0 * OUT_DIM, 0,
                    (size_t)(BATCH - TAIL_ROW0) * OUT_DIM * sizeof(float), 0);

    // 1) fused prep: materialize W (fp16) + convert x (fp16) in one launch
    prep_kernel<<<(unsigned)(W_BLOCKS + X_BLOCKS), 256>>>(
        codebook, x, (__half*)wptr, (__half*)xptr);

    // 2) GEMM (full tiles + split-K2 tail)
    static bool attr_set = false;
    if (!attr_set) {
        cudaFuncSetAttribute(gemm_kernel, cudaFuncAttributeMaxDynamicSharedMemorySize, SMEM_TOTAL);
        attr_set = true;
    }
    gemm_kernel<<<GRID_TOTAL, 128, SMEM_TOTAL>>>(
        (const __half*)xptr, (const __half*)wptr, bias, out);
}